// round 11
// baseline (speedup 1.0000x reference)
#include <cuda_runtime.h>
#include <cuda_fp16.h>
#include <cstdint>

#define NTOT   8192
#define DD     512
#define BHALF  4096
#define TILM   128
#define NCHUNK 4            // K=512 fp8 in chunks of 128B rows
#define NGRP   64           // 8192/128 row groups
#define NBLK   (NGRP * (NGRP + 1) / 2)   // 2080 triangular tiles
#define PGRID  444          // persistent grid: 3 CTAs/SM x 148 SMs
#define SCALE  2.885390081777927f        // 2 * log2(e)

// ---- device scratch (no allocations allowed) ----
// chunk-major pre-swizzled fp8: [group 64][chunk 4][16KB swizzled block]
__device__ uint4  g_za[NTOT * 32];      // z * SCALE (4 MB)
__device__ uint4  g_zb[NTOT * 32];      // z (4 MB)
__device__ float  g_pos[NTOT];
__device__ float  g_part[NGRP * NTOT];  // per-slot row partial denom sums (2 MB)
__device__ float  g_blk[256];
__device__ int    g_cnt;                // last-block-done counter (self-resetting)

// dynamic smem layout (bytes, after 1024-alignment)
#define OFF_A(b)   ((b) * 16384)            // A chunk buffers (2 x 16KB)
#define OFF_B(b)   (32768 + (b) * 16384)    // B chunk buffers (2 x 16KB)
#define OFF_REDR   65536                    // 128*4 floats
#define OFF_REDC   67584                    // 128*2 floats
#define OFF_MBAR   68608                    // 2 mbarriers
#define SMEM_DYN   69760                    // incl. 1KB alignment slack

__device__ __forceinline__ uint32_t smem_u32(const void* p) {
    uint32_t a;
    asm("{ .reg .u64 t; cvta.to.shared.u64 t, %1; cvt.u32.u64 %0, t; }" : "=r"(a) : "l"(p));
    return a;
}
__device__ __forceinline__ uint32_t swz(uint32_t off) {   // SW128 xor on 16B granules
    return off ^ ((off >> 3) & 0x70);
}
__device__ __forceinline__ void ldsm4(uint32_t* r, uint32_t addr) {
    asm volatile("ldmatrix.sync.aligned.m8n8.x4.shared.b16 {%0,%1,%2,%3}, [%4];"
                 : "=r"(r[0]), "=r"(r[1]), "=r"(r[2]), "=r"(r[3]) : "r"(addr));
}
// fp8 e4m3 mma with fp16 accumulators (2 packed c-regs)
__device__ __forceinline__ void mma16832h(uint32_t* c, const uint32_t* a,
                                          uint32_t b0, uint32_t b1) {
    asm volatile(
        "mma.sync.aligned.m16n8k32.row.col.f16.e4m3.e4m3.f16 "
        "{%0,%1}, {%2,%3,%4,%5}, {%6,%7}, {%0,%1};"
        : "+r"(c[0]), "+r"(c[1])
        : "r"(a[0]), "r"(a[1]), "r"(a[2]), "r"(a[3]), "r"(b0), "r"(b1));
}
__device__ __forceinline__ uint32_t pack4_e4m3(float x0, float x1, float x2, float x3) {
    uint16_t lo, hi;   // cvt packs: high byte = first operand, low byte = second
    asm("cvt.rn.satfinite.e4m3x2.f32 %0, %1, %2;" : "=h"(lo) : "f"(x1), "f"(x0));
    asm("cvt.rn.satfinite.e4m3x2.f32 %0, %1, %2;" : "=h"(hi) : "f"(x3), "f"(x2));
    return (uint32_t)lo | ((uint32_t)hi << 16);
}
__device__ __forceinline__ void bulk_ld(uint32_t dst, const void* src, uint32_t bytes,
                                        uint32_t mbar) {
    asm volatile("cp.async.bulk.shared::cluster.global.mbarrier::complete_tx::bytes "
                 "[%0], [%1], %2, [%3];"
                 :: "r"(dst), "l"(src), "r"(bytes), "r"(mbar) : "memory");
}

#define MBAR_WAIT(mbar, parity) do {                                           \
    uint32_t _m = (mbar), _p = (parity), _done;                                \
    asm volatile("{ .reg .pred p; mbarrier.try_wait.parity.acquire.cta.shared::cta.b64 p, [%1], %2; selp.b32 %0,1,0,p; }" \
                 : "=r"(_done) : "r"(_m), "r"(_p) : "memory");                 \
    if (!_done) {                                                              \
        asm volatile("{ .reg .pred P1; WL_%=: mbarrier.try_wait.parity.acquire.cta.shared::cta.b64 P1, [%0], %1, 0x989680; @P1 bra.uni WD_%=; bra.uni WL_%=; WD_%=: }" \
                     :: "r"(_m), "r"(_p) : "memory");                          \
    }                                                                          \
} while (0)

// ---- Kernel 1: fused normalize (fp8 emit, chunk-major pre-swizzled) + exact positives ----
// One block per pair i; ce staged through smem so each input byte is read once.
__global__ void kprep(const float* __restrict__ pe, const float* __restrict__ ce) {
    int i = blockIdx.x;
    int t = threadIdx.x;
    int half = t >> 7, u = t & 127;
    const float* rowp = half ? (ce + (size_t)i * DD) : (pe + (size_t)i * DD);
    float4 v = ((const float4*)rowp)[u];
    float ss = v.x * v.x + v.y * v.y + v.z * v.z + v.w * v.w;
#pragma unroll
    for (int o = 16; o > 0; o >>= 1) ss += __shfl_xor_sync(0xffffffffu, ss, o);
    __shared__ float wss[8], wsc[4];
    __shared__ float4 sce[128];
    if ((t & 31) == 0) wss[t >> 5] = ss;
    if (half) sce[u] = v;          // stage ce for the cross-dot (no second DRAM read)
    __syncthreads();

    if (half == 0) {
        float4 w = sce[u];
        float sc = v.x * w.x + v.y * w.y + v.z * w.z + v.w * w.w;
#pragma unroll
        for (int o = 16; o > 0; o >>= 1) sc += __shfl_xor_sync(0xffffffffu, sc, o);
        if ((t & 31) == 0) wsc[t >> 5] = sc;
    }
    __syncthreads();
    float na2 = wss[0] + wss[1] + wss[2] + wss[3];
    float nb2 = wss[4] + wss[5] + wss[6] + wss[7];
    float inv = 1.0f / fmaxf(sqrtf(half ? nb2 : na2), 1e-12f);
    float x0 = v.x * inv, x1 = v.y * inv, x2 = v.z * inv, x3 = v.w * inv;

    int row = half ? (i + BHALF) : i;
    size_t base = ((size_t)(row >> 7) * 4 + (u >> 5)) * 16384;   // chunk-major
    uint32_t off = swz((uint32_t)(((row & 127) << 7) | ((u << 2) & 127)));
    *(uint32_t*)((char*)g_zb + base + off) = pack4_e4m3(x0, x1, x2, x3);
    *(uint32_t*)((char*)g_za + base + off) =
        pack4_e4m3(x0 * SCALE, x1 * SCALE, x2 * SCALE, x3 * SCALE);

    if (t == 0) {
        float na = fmaxf(sqrtf(na2), 1e-12f);
        float nb = fmaxf(sqrtf(nb2), 1e-12f);
        float d = (wsc[0] + wsc[1] + wsc[2] + wsc[3]) / (na * nb);
        g_pos[i] = d;
        g_pos[i + BHALF] = d;
    }
}

__device__ __forceinline__ void decode_tri(int bid, int& it, int& jt) {
    jt = (int)((sqrtf(8.0f * (float)bid + 1.0f) - 1.0f) * 0.5f);
    while ((jt + 1) * (jt + 2) / 2 <= bid) jt++;
    while (jt * (jt + 1) / 2 > bid) jt--;
    it = bid - jt * (jt + 1) / 2;
}

// ------- Kernel 2: persistent triangular fp8 mma (fp16 acc), occ 3, streamed epilogue -------
__global__ __launch_bounds__(256, 3) void kgemm() {
    extern __shared__ char dsm_raw[];
    const uint32_t rawb = smem_u32(dsm_raw);
    const uint32_t sbase = (rawb + 1023) & ~1023u;
    char* dsm = dsm_raw + (sbase - rawb);

    const int tid = threadIdx.x;
    const int wid = tid >> 5, lid = tid & 31;
    const int wm = wid >> 2, wn = wid & 3;      // warp grid 2(M) x 4(N); warp tile 64x32

    if (tid == 0) {
        asm volatile("mbarrier.init.shared.b64 [%0], %1;"
                     :: "r"(sbase + OFF_MBAR), "r"(1u) : "memory");
        asm volatile("mbarrier.init.shared.b64 [%0], %1;"
                     :: "r"(sbase + OFF_MBAR + 8), "r"(1u) : "memory");
        asm volatile("fence.proxy.async.shared::cta;" ::: "memory");
    }
    __syncthreads();

    auto issue = [&](const char* A, const char* B, int ch, int bf) {
        if (tid == 0) {
            uint32_t mb = sbase + OFF_MBAR + bf * 8;
            asm volatile("mbarrier.arrive.expect_tx.shared.b64 _, [%0], %1;"
                         :: "r"(mb), "r"(32768u) : "memory");
            bulk_ld(sbase + OFF_A(bf), A + ch * 16384, 16384, mb);
            bulk_ld(sbase + OFF_B(bf), B + ch * 16384, 16384, mb);
        }
    };

    int w8[2] = {0, 0};     // per-buffer completed-wait counters (phase tracking)
    int bid = blockIdx.x;
    if (bid >= NBLK) return;
    int it, jt;
    decode_tri(bid, it, jt);
    const char* gA = (const char*)g_za + (size_t)it * 65536;
    const char* gB = (const char*)g_zb + (size_t)jt * 65536;
    issue(gA, gB, 0, 0);

    while (true) {
        uint32_t acc[4][4][2];
#pragma unroll
        for (int mi = 0; mi < 4; mi++)
#pragma unroll
            for (int n = 0; n < 4; n++) { acc[mi][n][0] = 0u; acc[mi][n][1] = 0u; }

        int nbid = bid + PGRID;
        int it2 = 0, jt2 = 0;
        const char *gA2 = nullptr, *gB2 = nullptr;

        for (int c = 0; c < NCHUNK; c++) {
            if (c < NCHUNK - 1) {
                issue(gA, gB, c + 1, (c + 1) & 1);
            } else if (nbid < NBLK) {      // prefetch next tile's chunk0 into free buf0
                decode_tri(nbid, it2, jt2);
                gA2 = (const char*)g_za + (size_t)it2 * 65536;
                gB2 = (const char*)g_zb + (size_t)jt2 * 65536;
                issue(gA2, gB2, 0, 0);
            }
            int bf = c & 1;
            MBAR_WAIT(sbase + OFF_MBAR + bf * 8, w8[bf] & 1);
            w8[bf]++;
            uint32_t abase = sbase + OFF_A(bf);
            uint32_t bbase = sbase + OFF_B(bf);
#pragma unroll
            for (int s = 0; s < 4; s++) {       // 4 x k32 slices per 128B chunk
                uint32_t kb = s * 32;
                uint32_t afr[4][4], bfr[2][4];
#pragma unroll
                for (int mi = 0; mi < 4; mi++) {
                    uint32_t row = wm * 64 + mi * 16 + (lid & 15);
                    ldsm4(afr[mi], abase + swz(row * 128 + kb + (lid >> 4) * 16));
                }
#pragma unroll
                for (int nq = 0; nq < 2; nq++) {
                    uint32_t row = wn * 32 + nq * 16 + (lid & 15);
                    ldsm4(bfr[nq], bbase + swz(row * 128 + kb + (lid >> 4) * 16));
                }
#pragma unroll
                for (int mi = 0; mi < 4; mi++)
#pragma unroll
                    for (int nq = 0; nq < 2; nq++)
#pragma unroll
                        for (int nh = 0; nh < 2; nh++)
                            mma16832h(acc[mi][nq * 2 + nh], afr[mi],
                                      bfr[nq][nh], bfr[nq][nh + 2]);
            }
            __syncthreads();   // all warps done before buffer reuse
        }

        // ---- streamed epilogue: per-mi unpack -> ex2 -> accumulate; low reg footprint ----
        float* redr = (float*)(dsm + OFF_REDR);   // [128][4]
        float* redc = (float*)(dsm + OFF_REDC);   // [128][2]
        float cs[4][2];                            // col partials carried across mi
#pragma unroll
        for (int n = 0; n < 4; n++) { cs[n][0] = 0.0f; cs[n][1] = 0.0f; }

#pragma unroll
        for (int mi = 0; mi < 4; mi++) {
            float rs0 = 0.0f, rs1 = 0.0f;
#pragma unroll
            for (int n = 0; n < 4; n++) {
                float2 lo = __half22float2(*(__half2*)&acc[mi][n][0]);
                float2 hi = __half22float2(*(__half2*)&acc[mi][n][1]);
                float e0, e1, e2, e3;
                asm("ex2.approx.f32 %0, %1;" : "=f"(e0) : "f"(lo.x));
                asm("ex2.approx.f32 %0, %1;" : "=f"(e1) : "f"(lo.y));
                asm("ex2.approx.f32 %0, %1;" : "=f"(e2) : "f"(hi.x));
                asm("ex2.approx.f32 %0, %1;" : "=f"(e3) : "f"(hi.y));
                rs0 += e0 + e1;                   // row lid>>2
                rs1 += e2 + e3;                   // row (lid>>2)+8
                cs[n][0] += e0 + e2;              // col (lid&3)*2
                cs[n][1] += e1 + e3;              // col (lid&3)*2+1
            }
            rs0 += __shfl_xor_sync(0xffffffffu, rs0, 1);
            rs0 += __shfl_xor_sync(0xffffffffu, rs0, 2);
            rs1 += __shfl_xor_sync(0xffffffffu, rs1, 1);
            rs1 += __shfl_xor_sync(0xffffffffu, rs1, 2);
            if ((lid & 3) == 0) {
                redr[(wm * 64 + mi * 16 + (lid >> 2)) * 4 + wn] = rs0;
                redr[(wm * 64 + mi * 16 + 8 + (lid >> 2)) * 4 + wn] = rs1;
            }
        }
#pragma unroll
        for (int n = 0; n < 4; n++)
#pragma unroll
            for (int cc = 0; cc < 2; cc++) {
                float v = cs[n][cc];
                v += __shfl_xor_sync(0xffffffffu, v, 4);
                v += __shfl_xor_sync(0xffffffffu, v, 8);
                v += __shfl_xor_sync(0xffffffffu, v, 16);
                if ((lid >> 2) == 0)
                    redc[(wn * 32 + n * 8 + (lid & 3) * 2 + cc) * 2 + wm] = v;
            }
        __syncthreads();

        if (tid < 128) {
            float rs = redr[tid * 4] + redr[tid * 4 + 1]
                     + redr[tid * 4 + 2] + redr[tid * 4 + 3];
            g_part[(size_t)jt * NTOT + it * TILM + tid] = rs;          // row side: slot jt
            if (it != jt) {
                float cv = redc[tid * 2] + redc[tid * 2 + 1];
                g_part[(size_t)it * NTOT + jt * TILM + tid] = cv;      // col side: slot it
            }
        }
        __syncthreads();   // redr/redc free before next tile's epilogue

        if (nbid >= NBLK) break;
        bid = nbid; it = it2; jt = jt2; gA = gA2; gB = gB2;
    }
}

// ---- Kernel 3: per-row loss + fused deterministic final reduction ----
__global__ void kfin1(float* out) {
    int t = threadIdx.x;               // 256
    int r = t & 31, seg = t >> 5;      // 8 segments x 32 rows
    int row = blockIdx.x * 32 + r;
    float d = 0.0f;
#pragma unroll
    for (int s = 0; s < 8; s++)
        d += g_part[(size_t)(seg * 8 + s) * NTOT + row];
    __shared__ float red[8][33];
    red[seg][r] = d;
    __syncthreads();
    if (t < 32) {
        float dd = 0.0f;
#pragma unroll
        for (int s = 0; s < 8; s++) dd += red[s][t];
        dd -= 7.3890561f;              // remove diagonal term exp(2)
        int row2 = blockIdx.x * 32 + t;
        float l = logf(dd) - g_pos[row2] * 2.0f;   // 1/T = 2
#pragma unroll
        for (int o = 16; o > 0; o >>= 1) l += __shfl_xor_sync(0xffffffffu, l, o);
        if (t == 0) g_blk[blockIdx.x] = l;
    }
    // last-block-done final sum (deterministic: fixed-order summation)
    __shared__ int is_last;
    __threadfence();
    __syncthreads();
    if (t == 0) is_last = (atomicAdd(&g_cnt, 1) == 255);
    __syncthreads();
    if (is_last) {
        float v = g_blk[t];
#pragma unroll
        for (int o = 16; o > 0; o >>= 1) v += __shfl_xor_sync(0xffffffffu, v, o);
        __shared__ float ws[8];
        if ((t & 31) == 0) ws[t >> 5] = v;
        __syncthreads();
        if (t == 0) {
            float s = 0.0f;
#pragma unroll
            for (int w = 0; w < 8; w++) s += ws[w];
            out[0] = s / (float)NTOT;
            g_cnt = 0;                 // reset for next graph replay
        }
    }
}

extern "C" void kernel_launch(void* const* d_in, const int* in_sizes, int n_in,
                              void* d_out, int out_size) {
    const float* pe = (const float*)d_in[0];
    const float* ce = (const float*)d_in[1];
    cudaFuncSetAttribute(kgemm, cudaFuncAttributeMaxDynamicSharedMemorySize, SMEM_DYN);
    kprep<<<BHALF, 256>>>(pe, ce);
    kgemm<<<PGRID, 256, SMEM_DYN>>>();
    kfin1<<<256, 256>>>((float*)d_out);
}

// round 13
// speedup vs baseline: 1.0386x; 1.0386x over previous
#include <cuda_runtime.h>
#include <cuda_fp16.h>
#include <cstdint>

#define NTOT   8192
#define DD     512
#define BHALF  4096
#define TILM   128
#define NCHUNK 4            // K=512 fp8 in chunks of 128B rows
#define NGRP   64           // 8192/128 row groups
#define NBLK   (NGRP * (NGRP + 1) / 2)   // 2080 triangular tiles
#define PGRID  296          // persistent grid: 2 CTAs/SM x 148 SMs
#define SCALE  2.885390081777927f        // 2 * log2(e)

// ---- device scratch (no allocations allowed) ----
// chunk-major pre-swizzled fp8: [group 64][chunk 4][16KB swizzled block]
__device__ uint4  g_za[NTOT * 32];      // z * SCALE (4 MB)
__device__ uint4  g_zb[NTOT * 32];      // z (4 MB)
__device__ float  g_pos[NTOT];
__device__ float  g_part[NGRP * NTOT];  // per-slot row partial denom sums (2 MB)
__device__ float  g_blk[256];
__device__ int    g_cnt;                // last-block-done counter (self-resetting)

// dynamic smem layout (bytes, after 1024-alignment)
#define OFF_A(b)   ((b) * 16384)            // A chunk buffers (2 x 16KB)
#define OFF_B(b)   (32768 + (b) * 16384)    // B chunk buffers (2 x 16KB)
#define OFF_REDR   65536                    // 128*4 floats
#define OFF_REDC   67584                    // 128*2 floats
#define OFF_MBAR   68608                    // 2 mbarriers
#define SMEM_DYN   69760                    // incl. 1KB alignment slack

__device__ __forceinline__ uint32_t smem_u32(const void* p) {
    uint32_t a;
    asm("{ .reg .u64 t; cvta.to.shared.u64 t, %1; cvt.u32.u64 %0, t; }" : "=r"(a) : "l"(p));
    return a;
}
__device__ __forceinline__ uint32_t swz(uint32_t off) {   // SW128 xor on 16B granules
    return off ^ ((off >> 3) & 0x70);
}
__device__ __forceinline__ void ldsm4(uint32_t* r, uint32_t addr) {
    asm volatile("ldmatrix.sync.aligned.m8n8.x4.shared.b16 {%0,%1,%2,%3}, [%4];"
                 : "=r"(r[0]), "=r"(r[1]), "=r"(r[2]), "=r"(r[3]) : "r"(addr));
}
// fp8 e4m3 mma with fp16 accumulators (2 packed c-regs)
__device__ __forceinline__ void mma16832h(uint32_t* c, const uint32_t* a,
                                          uint32_t b0, uint32_t b1) {
    asm volatile(
        "mma.sync.aligned.m16n8k32.row.col.f16.e4m3.e4m3.f16 "
        "{%0,%1}, {%2,%3,%4,%5}, {%6,%7}, {%0,%1};"
        : "+r"(c[0]), "+r"(c[1])
        : "r"(a[0]), "r"(a[1]), "r"(a[2]), "r"(a[3]), "r"(b0), "r"(b1));
}
__device__ __forceinline__ uint32_t pack4_e4m3(float x0, float x1, float x2, float x3) {
    uint16_t lo, hi;   // cvt packs: high byte = first operand, low byte = second
    asm("cvt.rn.satfinite.e4m3x2.f32 %0, %1, %2;" : "=h"(lo) : "f"(x1), "f"(x0));
    asm("cvt.rn.satfinite.e4m3x2.f32 %0, %1, %2;" : "=h"(hi) : "f"(x3), "f"(x2));
    return (uint32_t)lo | ((uint32_t)hi << 16);
}
__device__ __forceinline__ void bulk_ld(uint32_t dst, const void* src, uint32_t bytes,
                                        uint32_t mbar) {
    asm volatile("cp.async.bulk.shared::cluster.global.mbarrier::complete_tx::bytes "
                 "[%0], [%1], %2, [%3];"
                 :: "r"(dst), "l"(src), "r"(bytes), "r"(mbar) : "memory");
}

#define MBAR_WAIT(mbar, parity) do {                                           \
    uint32_t _m = (mbar), _p = (parity), _done;                                \
    asm volatile("{ .reg .pred p; mbarrier.try_wait.parity.acquire.cta.shared::cta.b64 p, [%1], %2; selp.b32 %0,1,0,p; }" \
                 : "=r"(_done) : "r"(_m), "r"(_p) : "memory");                 \
    if (!_done) {                                                              \
        asm volatile("{ .reg .pred P1; WL_%=: mbarrier.try_wait.parity.acquire.cta.shared::cta.b64 P1, [%0], %1, 0x989680; @P1 bra.uni WD_%=; bra.uni WL_%=; WD_%=: }" \
                     :: "r"(_m), "r"(_p) : "memory");                          \
    }                                                                          \
} while (0)

// ---- Kernel 1: fused normalize (fp8 emit, chunk-major pre-swizzled) + exact positives ----
__global__ void kprep(const float* __restrict__ pe, const float* __restrict__ ce) {
    int i = blockIdx.x;
    int t = threadIdx.x;
    int half = t >> 7, u = t & 127;
    const float* rowp = half ? (ce + (size_t)i * DD) : (pe + (size_t)i * DD);
    float4 v = ((const float4*)rowp)[u];
    float ss = v.x * v.x + v.y * v.y + v.z * v.z + v.w * v.w;
#pragma unroll
    for (int o = 16; o > 0; o >>= 1) ss += __shfl_xor_sync(0xffffffffu, ss, o);
    __shared__ float wss[8], wsc[4];
    __shared__ float4 sce[128];
    if ((t & 31) == 0) wss[t >> 5] = ss;
    if (half) sce[u] = v;          // stage ce for the cross-dot (single DRAM read)
    __syncthreads();

    if (half == 0) {
        float4 w = sce[u];
        float sc = v.x * w.x + v.y * w.y + v.z * w.z + v.w * w.w;
#pragma unroll
        for (int o = 16; o > 0; o >>= 1) sc += __shfl_xor_sync(0xffffffffu, sc, o);
        if ((t & 31) == 0) wsc[t >> 5] = sc;
    }
    __syncthreads();
    float na2 = wss[0] + wss[1] + wss[2] + wss[3];
    float nb2 = wss[4] + wss[5] + wss[6] + wss[7];
    float inv = 1.0f / fmaxf(sqrtf(half ? nb2 : na2), 1e-12f);
    float x0 = v.x * inv, x1 = v.y * inv, x2 = v.z * inv, x3 = v.w * inv;

    int row = half ? (i + BHALF) : i;
    size_t base = ((size_t)(row >> 7) * 4 + (u >> 5)) * 16384;   // chunk-major
    uint32_t off = swz((uint32_t)(((row & 127) << 7) | ((u << 2) & 127)));
    *(uint32_t*)((char*)g_zb + base + off) = pack4_e4m3(x0, x1, x2, x3);
    *(uint32_t*)((char*)g_za + base + off) =
        pack4_e4m3(x0 * SCALE, x1 * SCALE, x2 * SCALE, x3 * SCALE);

    if (t == 0) {
        float na = fmaxf(sqrtf(na2), 1e-12f);
        float nb = fmaxf(sqrtf(nb2), 1e-12f);
        float d = (wsc[0] + wsc[1] + wsc[2] + wsc[3]) / (na * nb);
        g_pos[i] = d;
        g_pos[i + BHALF] = d;
    }
}

__device__ __forceinline__ void decode_tri(int bid, int& it, int& jt) {
    jt = (int)((sqrtf(8.0f * (float)bid + 1.0f) - 1.0f) * 0.5f);
    while ((jt + 1) * (jt + 2) / 2 <= bid) jt++;
    while (jt * (jt + 1) / 2 > bid) jt--;
    it = bid - jt * (jt + 1) / 2;
}

// ------- Kernel 2: persistent triangular fp8 mma (fp16 acc), occ 2, pipelined fragments -------
__global__ __launch_bounds__(256, 2) void kgemm() {
    extern __shared__ char dsm_raw[];
    const uint32_t rawb = smem_u32(dsm_raw);
    const uint32_t sbase = (rawb + 1023) & ~1023u;
    char* dsm = dsm_raw + (sbase - rawb);

    const int tid = threadIdx.x;
    const int wid = tid >> 5, lid = tid & 31;
    const int wm = wid >> 2, wn = wid & 3;      // warp grid 2(M) x 4(N); warp tile 64x32

    if (tid == 0) {
        asm volatile("mbarrier.init.shared.b64 [%0], %1;"
                     :: "r"(sbase + OFF_MBAR), "r"(1u) : "memory");
        asm volatile("mbarrier.init.shared.b64 [%0], %1;"
                     :: "r"(sbase + OFF_MBAR + 8), "r"(1u) : "memory");
        asm volatile("fence.proxy.async.shared::cta;" ::: "memory");
    }
    __syncthreads();

    auto issue = [&](const char* A, const char* B, int ch, int bf) {
        if (tid == 0) {
            uint32_t mb = sbase + OFF_MBAR + bf * 8;
            asm volatile("mbarrier.arrive.expect_tx.shared.b64 _, [%0], %1;"
                         :: "r"(mb), "r"(32768u) : "memory");
            bulk_ld(sbase + OFF_A(bf), A + ch * 16384, 16384, mb);
            bulk_ld(sbase + OFF_B(bf), B + ch * 16384, 16384, mb);
        }
    };

    // per-slice fragment load (into register buffer p)
    const uint32_t arow = wm * 64 + (lid & 15);
    const uint32_t brow = wn * 32 + (lid & 15);
    const uint32_t koff = (lid >> 4) * 16;

    int w8[2] = {0, 0};     // per-buffer completed-wait counters (phase tracking)
    int bid = blockIdx.x;
    if (bid >= NBLK) return;
    int it, jt;
    decode_tri(bid, it, jt);
    const char* gA = (const char*)g_za + (size_t)it * 65536;
    const char* gB = (const char*)g_zb + (size_t)jt * 65536;
    issue(gA, gB, 0, 0);

    while (true) {
        uint32_t acc[4][4][2];
#pragma unroll
        for (int mi = 0; mi < 4; mi++)
#pragma unroll
            for (int n = 0; n < 4; n++) { acc[mi][n][0] = 0u; acc[mi][n][1] = 0u; }

        int nbid = bid + PGRID;
        int it2 = 0, jt2 = 0;
        const char *gA2 = nullptr, *gB2 = nullptr;

        uint32_t afr[2][4][4], bfr[2][2][4];   // double-buffered fragments

        for (int c = 0; c < NCHUNK; c++) {
            if (c < NCHUNK - 1) {
                issue(gA, gB, c + 1, (c + 1) & 1);
            } else if (nbid < NBLK) {      // prefetch next tile's chunk0 into free buf0
                decode_tri(nbid, it2, jt2);
                gA2 = (const char*)g_za + (size_t)it2 * 65536;
                gB2 = (const char*)g_zb + (size_t)jt2 * 65536;
                issue(gA2, gB2, 0, 0);
            }
            int bf = c & 1;
            MBAR_WAIT(sbase + OFF_MBAR + bf * 8, w8[bf] & 1);
            w8[bf]++;
            uint32_t abase = sbase + OFF_A(bf);
            uint32_t bbase = sbase + OFF_B(bf);

            // prologue: slice 0 fragments
#pragma unroll
            for (int mi = 0; mi < 4; mi++)
                ldsm4(afr[0][mi], abase + swz((arow + mi * 16) * 128 + koff));
#pragma unroll
            for (int nq = 0; nq < 2; nq++)
                ldsm4(bfr[0][nq], bbase + swz((brow + nq * 16) * 128 + koff));

#pragma unroll
            for (int s = 0; s < 4; s++) {       // pipelined: ldsm s+1 before mma s
                int pc = s & 1, pn = pc ^ 1;
                if (s < 3) {
                    uint32_t kb = (s + 1) * 32;
#pragma unroll
                    for (int mi = 0; mi < 4; mi++)
                        ldsm4(afr[pn][mi], abase + swz((arow + mi * 16) * 128 + kb + koff));
#pragma unroll
                    for (int nq = 0; nq < 2; nq++)
                        ldsm4(bfr[pn][nq], bbase + swz((brow + nq * 16) * 128 + kb + koff));
                }
#pragma unroll
                for (int mi = 0; mi < 4; mi++)
#pragma unroll
                    for (int nq = 0; nq < 2; nq++)
#pragma unroll
                        for (int nh = 0; nh < 2; nh++)
                            mma16832h(acc[mi][nq * 2 + nh], afr[pc][mi],
                                      bfr[pc][nq][nh], bfr[pc][nq][nh + 2]);
            }
            __syncthreads();   // all warps done before buffer reuse
        }

        // ---- streamed epilogue: per-mi unpack -> ex2 -> accumulate ----
        float* redr = (float*)(dsm + OFF_REDR);   // [128][4]
        float* redc = (float*)(dsm + OFF_REDC);   // [128][2]
        float cs[4][2];                            // col partials carried across mi
#pragma unroll
        for (int n = 0; n < 4; n++) { cs[n][0] = 0.0f; cs[n][1] = 0.0f; }

#pragma unroll
        for (int mi = 0; mi < 4; mi++) {
            float rs0 = 0.0f, rs1 = 0.0f;
#pragma unroll
            for (int n = 0; n < 4; n++) {
                float2 lo = __half22float2(*(__half2*)&acc[mi][n][0]);
                float2 hi = __half22float2(*(__half2*)&acc[mi][n][1]);
                float e0, e1, e2, e3;
                asm("ex2.approx.f32 %0, %1;" : "=f"(e0) : "f"(lo.x));
                asm("ex2.approx.f32 %0, %1;" : "=f"(e1) : "f"(lo.y));
                asm("ex2.approx.f32 %0, %1;" : "=f"(e2) : "f"(hi.x));
                asm("ex2.approx.f32 %0, %1;" : "=f"(e3) : "f"(hi.y));
                rs0 += e0 + e1;                   // row lid>>2
                rs1 += e2 + e3;                   // row (lid>>2)+8
                cs[n][0] += e0 + e2;              // col (lid&3)*2
                cs[n][1] += e1 + e3;              // col (lid&3)*2+1
            }
            rs0 += __shfl_xor_sync(0xffffffffu, rs0, 1);
            rs0 += __shfl_xor_sync(0xffffffffu, rs0, 2);
            rs1 += __shfl_xor_sync(0xffffffffu, rs1, 1);
            rs1 += __shfl_xor_sync(0xffffffffu, rs1, 2);
            if ((lid & 3) == 0) {
                redr[(wm * 64 + mi * 16 + (lid >> 2)) * 4 + wn] = rs0;
                redr[(wm * 64 + mi * 16 + 8 + (lid >> 2)) * 4 + wn] = rs1;
            }
        }
#pragma unroll
        for (int n = 0; n < 4; n++)
#pragma unroll
            for (int cc = 0; cc < 2; cc++) {
                float v = cs[n][cc];
                v += __shfl_xor_sync(0xffffffffu, v, 4);
                v += __shfl_xor_sync(0xffffffffu, v, 8);
                v += __shfl_xor_sync(0xffffffffu, v, 16);
                if ((lid >> 2) == 0)
                    redc[(wn * 32 + n * 8 + (lid & 3) * 2 + cc) * 2 + wm] = v;
            }
        __syncthreads();

        if (tid < 128) {
            float rs = redr[tid * 4] + redr[tid * 4 + 1]
                     + redr[tid * 4 + 2] + redr[tid * 4 + 3];
            g_part[(size_t)jt * NTOT + it * TILM + tid] = rs;          // row side: slot jt
            if (it != jt) {
                float cv = redc[tid * 2] + redc[tid * 2 + 1];
                g_part[(size_t)it * NTOT + jt * TILM + tid] = cv;      // col side: slot it
            }
        }
        __syncthreads();   // redr/redc free before next tile's epilogue

        if (nbid >= NBLK) break;
        bid = nbid; it = it2; jt = jt2; gA = gA2; gB = gB2;
    }
}

// ---- Kernel 3: per-row loss + fused deterministic final reduction ----
__global__ void kfin1(float* out) {
    int t = threadIdx.x;               // 256
    int r = t & 31, seg = t >> 5;      // 8 segments x 32 rows
    int row = blockIdx.x * 32 + r;
    float d = 0.0f;
#pragma unroll
    for (int s = 0; s < 8; s++)
        d += g_part[(size_t)(seg * 8 + s) * NTOT + row];
    __shared__ float red[8][33];
    red[seg][r] = d;
    __syncthreads();
    if (t < 32) {
        float dd = 0.0f;
#pragma unroll
        for (int s = 0; s < 8; s++) dd += red[s][t];
        dd -= 7.3890561f;              // remove diagonal term exp(2)
        int row2 = blockIdx.x * 32 + t;
        float l = logf(dd) - g_pos[row2] * 2.0f;   // 1/T = 2
#pragma unroll
        for (int o = 16; o > 0; o >>= 1) l += __shfl_xor_sync(0xffffffffu, l, o);
        if (t == 0) g_blk[blockIdx.x] = l;
    }
    // last-block-done final sum (deterministic: fixed-order summation)
    __shared__ int is_last;
    __threadfence();
    __syncthreads();
    if (t == 0) is_last = (atomicAdd(&g_cnt, 1) == 255);
    __syncthreads();
    if (is_last) {
        float v = g_blk[t];
#pragma unroll
        for (int o = 16; o > 0; o >>= 1) v += __shfl_xor_sync(0xffffffffu, v, o);
        __shared__ float ws[8];
        if ((t & 31) == 0) ws[t >> 5] = v;
        __syncthreads();
        if (t == 0) {
            float s = 0.0f;
#pragma unroll
            for (int w = 0; w < 8; w++) s += ws[w];
            out[0] = s / (float)NTOT;
            g_cnt = 0;                 // reset for next graph replay
        }
    }
}

extern "C" void kernel_launch(void* const* d_in, const int* in_sizes, int n_in,
                              void* d_out, int out_size) {
    const float* pe = (const float*)d_in[0];
    const float* ce = (const float*)d_in[1];
    cudaFuncSetAttribute(kgemm, cudaFuncAttributeMaxDynamicSharedMemorySize, SMEM_DYN);
    kprep<<<BHALF, 256>>>(pe, ce);
    kgemm<<<PGRID, 256, SMEM_DYN>>>();
    kfin1<<<256, 256>>>((float*)d_out);
}